// round 2
// baseline (speedup 1.0000x reference)
#include <cuda_runtime.h>
#include <math.h>

#define NN 8192
#define DD 64
#define TILE 128
#define BK 32
#define NT (NN / TILE)   // 64 tiles per dim

// Scratch (allocation-free rule: __device__ globals)
__device__ float g_Xs[NN * DD];   // X * sqrt(params), 2 MB (L2-resident)
__device__ float g_sq[NN];        // row squared norms of Xs
__device__ double g_num;
__device__ double g_den;

// ---------------------------------------------------------------------------
// Prep: Xs = X * sqrt(params); sq[i] = ||Xs_i||^2 ; reset accumulators.
// One warp per row (D=64 -> 2 elems/lane).
// ---------------------------------------------------------------------------
__global__ void prep_kernel(const float* __restrict__ X,
                            const float* __restrict__ params) {
    if (blockIdx.x == 0 && threadIdx.x == 0) { g_num = 0.0; g_den = 0.0; }
    int gwarp = (blockIdx.x * blockDim.x + threadIdx.x) >> 5;
    int lane  = threadIdx.x & 31;
    if (gwarp >= NN) return;

    float p0 = sqrtf(params[lane]);
    float p1 = sqrtf(params[lane + 32]);
    float x0 = X[gwarp * DD + lane]      * p0;
    float x1 = X[gwarp * DD + lane + 32] * p1;
    g_Xs[gwarp * DD + lane]      = x0;
    g_Xs[gwarp * DD + lane + 32] = x1;

    float s = x0 * x0 + x1 * x1;
    #pragma unroll
    for (int o = 16; o; o >>= 1) s += __shfl_xor_sync(0xFFFFFFFFu, s, o);
    if (lane == 0) g_sq[gwarp] = s;
}

// ---------------------------------------------------------------------------
// Main: for tile pair (bi, bj), bi <= bj, compute 128x128 block of
// K = exp(-max(sq_i + sq_j - 2 Xs_i.Xs_j, 0)), with K[i,i] forced to 1,
// and accumulate  num += w * t_i t_j K ,  den += w * K^2  (w=2 off-diag tiles).
// 8x8 microtile per thread, strided (i = ty + 16u, j = tx + 16v).
// ---------------------------------------------------------------------------
__global__ __launch_bounds__(256, 2)
void tile_kernel(const float* __restrict__ target) {
    const int bi = blockIdx.y;
    const int bj = blockIdx.x;
    if (bj < bi) return;  // triangular: symmetry

    __shared__ float As[BK][TILE + 1];  // [k][row], pad 1 -> conflict-free STS
    __shared__ float Bs[BK][TILE + 1];

    const int tid = threadIdx.x;
    const int tx  = tid & 15;
    const int ty  = tid >> 4;

    float acc[8][8];
    #pragma unroll
    for (int u = 0; u < 8; u++)
        #pragma unroll
        for (int v = 0; v < 8; v++) acc[u][v] = 0.0f;

    const float* __restrict__ Abase = g_Xs + (size_t)bi * TILE * DD;
    const float* __restrict__ Bbase = g_Xs + (size_t)bj * TILE * DD;

    #pragma unroll
    for (int kc = 0; kc < DD; kc += BK) {
        // Stage chunk: 128 rows x 32 k. Warp covers one row (32 consecutive k)
        // -> coalesced LDG 128B; STS banks = k*(129) mod 32 = k -> conflict-free.
        #pragma unroll
        for (int s = 0; s < 16; s++) {
            int e   = tid + 256 * s;
            int row = e >> 5;
            int kk  = e & 31;
            As[kk][row] = Abase[row * DD + kc + kk];
            Bs[kk][row] = Bbase[row * DD + kc + kk];
        }
        __syncthreads();

        #pragma unroll
        for (int k = 0; k < BK; k++) {
            float a[8], b[8];
            #pragma unroll
            for (int u = 0; u < 8; u++) a[u] = As[k][ty + 16 * u];  // broadcast
            #pragma unroll
            for (int v = 0; v < 8; v++) b[v] = Bs[k][tx + 16 * v];  // contiguous
            #pragma unroll
            for (int u = 0; u < 8; u++)
                #pragma unroll
                for (int v = 0; v < 8; v++)
                    acc[u][v] = fmaf(a[u], b[v], acc[u][v]);
        }
        __syncthreads();
    }

    // Epilogue: fused exp + reductions (K never materialized)
    float sqi[8], sqj[8], ti[8], tj[8];
    #pragma unroll
    for (int u = 0; u < 8; u++) {
        int i = bi * TILE + ty + 16 * u;
        sqi[u] = g_sq[i];
        ti[u]  = target[i];
    }
    #pragma unroll
    for (int v = 0; v < 8; v++) {
        int j = bj * TILE + tx + 16 * v;
        sqj[v] = g_sq[j];
        tj[v]  = target[j];
    }

    const bool diag = (bi == bj);
    float ln = 0.0f, ld = 0.0f;
    #pragma unroll
    for (int u = 0; u < 8; u++) {
        #pragma unroll
        for (int v = 0; v < 8; v++) {
            float d2 = fmaxf(sqi[u] + sqj[v] - 2.0f * acc[u][v], 0.0f);
            float Kv = __expf(-d2);
            if (diag && (ty + 16 * u) == (tx + 16 * v)) Kv = 1.0f;  // match ref diag
            ln = fmaf(ti[u] * tj[v], Kv, ln);
            ld = fmaf(Kv, Kv, ld);
        }
    }
    const float w = diag ? 1.0f : 2.0f;
    ln *= w;
    ld *= w;

    // Block reduction -> double atomics
    #pragma unroll
    for (int o = 16; o; o >>= 1) {
        ln += __shfl_xor_sync(0xFFFFFFFFu, ln, o);
        ld += __shfl_xor_sync(0xFFFFFFFFu, ld, o);
    }
    __shared__ float rn[8], rd[8];
    int wid = tid >> 5, lane = tid & 31;
    if (lane == 0) { rn[wid] = ln; rd[wid] = ld; }
    __syncthreads();
    if (tid == 0) {
        float a = 0.0f, b = 0.0f;
        #pragma unroll
        for (int i = 0; i < 8; i++) { a += rn[i]; b += rd[i]; }
        atomicAdd(&g_num, (double)a);
        atomicAdd(&g_den, (double)b);
    }
}

__global__ void fin_kernel(float* __restrict__ out) {
    out[0] = (float)(-g_num / ((double)NN * sqrt(g_den)));
}

extern "C" void kernel_launch(void* const* d_in, const int* in_sizes, int n_in,
                              void* d_out, int out_size) {
    const float* X      = (const float*)d_in[0];
    const float* target = (const float*)d_in[1];
    const float* params = (const float*)d_in[2];
    float* out = (float*)d_out;

    prep_kernel<<<NN / 8, 256>>>(X, params);          // 8 warps/block, 1 row/warp
    tile_kernel<<<dim3(NT, NT), 256>>>(target);       // upper-triangular tile pairs
    fin_kernel<<<1, 1>>>(out);
}

// round 10
// speedup vs baseline: 3.5282x; 3.5282x over previous
#include <cuda_runtime.h>
#include <cuda_bf16.h>
#include <math.h>

#define NN 8192
#define DD 64
#define TILE 128
#define NT (NN / TILE)                 // 64 tiles per dim
#define NPAIRS (NT * (NT + 1) / 2)     // 2080 triangular tile pairs
#define TILE_BYTES (TILE * DD * 2)     // 16 KB: 128 rows x 64 bf16 (128 B/row)

// ---------------------------------------------------------------------------
// Scratch (__device__ globals; allocation-free rule)
// ---------------------------------------------------------------------------
__device__ __align__(16) unsigned char g_Xsb[NT * TILE_BYTES]; // swizzled bf16 tiles (4 MB, L2-resident)
__device__ float g_sq[NN];
__device__ double g_num, g_den;

__device__ __forceinline__ unsigned smem_u32(const void* p) {
    unsigned a;
    asm("{ .reg .u64 t; cvta.to.shared.u64 t, %1; cvt.u32.u64 %0, t; }" : "=r"(a) : "l"(p));
    return a;
}

// m16n8k16 bf16 MMA, D += A*B (fp32 acc). Supported on plain sm_103 (sm_80+).
__device__ __forceinline__ void mma16816(float* d, const unsigned* a, const unsigned* b) {
    asm volatile(
        "mma.sync.aligned.m16n8k16.row.col.f32.bf16.bf16.f32 "
        "{%0,%1,%2,%3}, {%4,%5,%6,%7}, {%8,%9}, {%0,%1,%2,%3};"
        : "+f"(d[0]), "+f"(d[1]), "+f"(d[2]), "+f"(d[3])
        : "r"(a[0]), "r"(a[1]), "r"(a[2]), "r"(a[3]), "r"(b[0]), "r"(b[1]));
}

__device__ __forceinline__ void ldsm_x4(unsigned* r, unsigned addr) {
    asm volatile("ldmatrix.sync.aligned.m8n8.x4.shared.b16 {%0,%1,%2,%3}, [%4];"
                 : "=r"(r[0]), "=r"(r[1]), "=r"(r[2]), "=r"(r[3]) : "r"(addr));
}

// ---------------------------------------------------------------------------
// Prep: Xs = X*sqrt(params) -> bf16, stored per-tile with 8-row XOR swizzle:
// element (row, e): byte = row*128 + (((e>>3) ^ (row&7))<<4) + (e&7)*2.
// sq[i] = ||Xs_i||^2 (fp32 exact). One warp per row.
// ---------------------------------------------------------------------------
__global__ void prep_kernel(const float* __restrict__ X,
                            const float* __restrict__ params) {
    if (blockIdx.x == 0 && threadIdx.x == 0) { g_num = 0.0; g_den = 0.0; }
    int row  = (blockIdx.x * blockDim.x + threadIdx.x) >> 5;
    int lane = threadIdx.x & 31;
    if (row >= NN) return;

    float p0 = sqrtf(params[lane]);
    float p1 = sqrtf(params[lane + 32]);
    float x0 = X[row * DD + lane]      * p0;
    float x1 = X[row * DD + lane + 32] * p1;

    int tile = row >> 7, ri = row & 127;
    unsigned char* tb = g_Xsb + (size_t)tile * TILE_BYTES;
    int e0 = lane, e1 = lane + 32;
    unsigned o0 = ri * 128 + ((((unsigned)e0 >> 3) ^ (ri & 7)) << 4) + (e0 & 7) * 2;
    unsigned o1 = ri * 128 + ((((unsigned)e1 >> 3) ^ (ri & 7)) << 4) + (e1 & 7) * 2;
    *(__nv_bfloat16*)(tb + o0) = __float2bfloat16(x0);
    *(__nv_bfloat16*)(tb + o1) = __float2bfloat16(x1);

    float s = x0 * x0 + x1 * x1;
    #pragma unroll
    for (int o = 16; o; o >>= 1) s += __shfl_xor_sync(0xFFFFFFFFu, s, o);
    if (lane == 0) g_sq[row] = s;
}

// ---------------------------------------------------------------------------
// Persistent HMMA tile kernel: grid-stride over 2080 triangular pairs.
// 8 warps as 2x4 grid; each warp 64x32 subtile = 4x4 m16n8k16 atoms.
// Accumulators stay in registers; fused exp + reductions epilogue.
// ---------------------------------------------------------------------------
__global__ __launch_bounds__(256, 2)
void tile_kernel(const float* __restrict__ target) {
    __shared__ __align__(16) unsigned char As[TILE_BYTES];
    __shared__ __align__(16) unsigned char Bs[TILE_BYTES];
    __shared__ float s_sqi[TILE], s_ti[TILE], s_sqj[TILE], s_tj[TILE];

    const int tid  = threadIdx.x;
    const int wid  = tid >> 5;
    const int lane = tid & 31;
    const int wr   = wid >> 2;     // 0..1 : row block of 64
    const int wc   = wid & 3;      // 0..3 : col block of 32
    const int gid  = lane >> 2;    // mma groupID
    const int tig  = lane & 3;     // mma thread-in-group

    const unsigned sA = smem_u32(As);
    const unsigned sB = smem_u32(Bs);

    // ldmatrix lane address components (constant over kstep/atom):
    //   A x4 mats: [rows ra*16+0..7, kchunk c] [rows +8, c] [rows, c+1] [rows +8, c+1]
    //   lanes 0-7 -> mat0 rows, 8-15 -> mat1, 16-23 -> mat2, 24-31 -> mat3
    const int l7 = lane & 7;
    const int a_row = 64 * wr + 8 * ((lane >> 3) & 1) + l7;  // + 16*ra
    const int a_cp  = lane >> 4;                             // chunk parity
    const int b_row = 32 * wc + 8 * (lane >> 4) + l7;        // + 16*cb
    const int b_cp  = (lane >> 3) & 1;

    float ln = 0.0f, ld = 0.0f;

    for (int t = blockIdx.x; t < NPAIRS; t += gridDim.x) {
        // decode triangular pair (bi <= bj)
        int rem = t, bi = 0;
        while (rem >= NT - bi) { rem -= NT - bi; bi++; }
        const int bj = bi + rem;

        // stage tiles (linear vectorized copy; swizzle already applied in gmem)
        {
            const uint4* Ag = (const uint4*)(g_Xsb + (size_t)bi * TILE_BYTES);
            const uint4* Bg = (const uint4*)(g_Xsb + (size_t)bj * TILE_BYTES);
            uint4* As4 = (uint4*)As;
            uint4* Bs4 = (uint4*)Bs;
            #pragma unroll
            for (int s = 0; s < 4; s++) {
                As4[tid + 256 * s] = Ag[tid + 256 * s];
                Bs4[tid + 256 * s] = Bg[tid + 256 * s];
            }
            if (tid < 128) {
                s_sqi[tid] = g_sq[bi * TILE + tid];
                s_ti[tid]  = target[bi * TILE + tid];
            } else {
                s_sqj[tid - 128] = g_sq[bj * TILE + tid - 128];
                s_tj[tid - 128]  = target[bj * TILE + tid - 128];
            }
        }
        __syncthreads();

        // ---- MMA mainloop: K=64 as 4 steps of 16 ----
        float acc[4][4][4];
        #pragma unroll
        for (int ra = 0; ra < 4; ra++)
            #pragma unroll
            for (int ca = 0; ca < 4; ca++)
                #pragma unroll
                for (int q = 0; q < 4; q++) acc[ra][ca][q] = 0.0f;

        #pragma unroll
        for (int ks = 0; ks < 4; ks++) {
            const unsigned axor = (((unsigned)(2 * ks + a_cp)) ^ (unsigned)l7) << 4;
            const unsigned bxor = (((unsigned)(2 * ks + b_cp)) ^ (unsigned)l7) << 4;

            unsigned a[4][4];
            #pragma unroll
            for (int ra = 0; ra < 4; ra++)
                ldsm_x4(a[ra], sA + (unsigned)(a_row + 16 * ra) * 128 + axor);

            // B x4 mats: [cb rows, c] [cb rows, c+1] [cb+8.. (ca odd) rows, c] [.., c+1]
            unsigned b[2][4];
            #pragma unroll
            for (int cb = 0; cb < 2; cb++)
                ldsm_x4(b[cb], sB + (unsigned)(b_row + 16 * cb) * 128 + bxor);

            #pragma unroll
            for (int ra = 0; ra < 4; ra++)
                #pragma unroll
                for (int ca = 0; ca < 4; ca++)
                    mma16816(acc[ra][ca], a[ra], &b[ca >> 1][(ca & 1) * 2]);
        }

        // ---- fused epilogue: exp + both reductions, all in registers ----
        const bool diag = (bi == bj);
        float tn = 0.0f, td = 0.0f;
        #pragma unroll
        for (int ra = 0; ra < 4; ra++) {
            const int r0 = 64 * wr + 16 * ra + gid;   // local row of d0,d1
            const int r1 = r0 + 8;                    // local row of d2,d3
            const float sqi0 = s_sqi[r0], ti0 = s_ti[r0];
            const float sqi1 = s_sqi[r1], ti1 = s_ti[r1];
            #pragma unroll
            for (int ca = 0; ca < 4; ca++) {
                const int c0 = 32 * wc + 8 * ca + 2 * tig;
                const float sqj0 = s_sqj[c0],     tj0 = s_tj[c0];
                const float sqj1 = s_sqj[c0 + 1], tj1 = s_tj[c0 + 1];
                const float* d = acc[ra][ca];

                float K00 = __expf(-fmaxf(sqi0 + sqj0 - 2.0f * d[0], 0.0f));
                float K01 = __expf(-fmaxf(sqi0 + sqj1 - 2.0f * d[1], 0.0f));
                float K10 = __expf(-fmaxf(sqi1 + sqj0 - 2.0f * d[2], 0.0f));
                float K11 = __expf(-fmaxf(sqi1 + sqj1 - 2.0f * d[3], 0.0f));
                if (diag) {   // reference keeps eye() on the diagonal
                    if (r0 == c0)     K00 = 1.0f;
                    if (r0 == c0 + 1) K01 = 1.0f;
                    if (r1 == c0)     K10 = 1.0f;
                    if (r1 == c0 + 1) K11 = 1.0f;
                }
                tn = fmaf(ti0 * tj0, K00, tn);
                tn = fmaf(ti0 * tj1, K01, tn);
                tn = fmaf(ti1 * tj0, K10, tn);
                tn = fmaf(ti1 * tj1, K11, tn);
                td = fmaf(K00, K00, td);
                td = fmaf(K01, K01, td);
                td = fmaf(K10, K10, td);
                td = fmaf(K11, K11, td);
            }
        }
        const float w = diag ? 1.0f : 2.0f;   // symmetry: off-diag pairs counted twice
        ln = fmaf(w, tn, ln);
        ld = fmaf(w, td, ld);

        __syncthreads();   // done with smem -> safe to restage next tile
    }

    // block reduction -> double atomics
    #pragma unroll
    for (int o = 16; o; o >>= 1) {
        ln += __shfl_xor_sync(0xFFFFFFFFu, ln, o);
        ld += __shfl_xor_sync(0xFFFFFFFFu, ld, o);
    }
    __shared__ float rn[8], rd[8];
    if (lane == 0) { rn[wid] = ln; rd[wid] = ld; }
    __syncthreads();
    if (tid == 0) {
        float a = 0.0f, b = 0.0f;
        #pragma unroll
        for (int k = 0; k < 8; k++) { a += rn[k]; b += rd[k]; }
        atomicAdd(&g_num, (double)a);
        atomicAdd(&g_den, (double)b);
    }
}

__global__ void fin_kernel(float* __restrict__ out) {
    out[0] = (float)(-g_num / ((double)NN * sqrt(g_den)));
}

extern "C" void kernel_launch(void* const* d_in, const int* in_sizes, int n_in,
                              void* d_out, int out_size) {
    const float* X      = (const float*)d_in[0];
    const float* target = (const float*)d_in[1];
    const float* params = (const float*)d_in[2];
    float* out = (float*)d_out;

    prep_kernel<<<NN / 8, 256>>>(X, params);
    tile_kernel<<<296, 256>>>(target);   // persistent, 2 CTAs/SM
    fin_kernel<<<1, 1>>>(out);
}

// round 11
// speedup vs baseline: 3.9379x; 1.1161x over previous
#include <cuda_runtime.h>
#include <cuda_bf16.h>
#include <math.h>

#define NN 8192
#define DD 64
#define TILE 128
#define NT (NN / TILE)                 // 64 tiles per dim
#define NPAIRS (NT * (NT + 1) / 2)     // 2080 triangular tile pairs
#define TILE_BYTES (TILE * DD * 2)     // 16 KB: 128 rows x 64 bf16 (128 B/row)
#define BUF_BYTES (2 * TILE_BYTES)     // A + B per stage
#define GRID_TILE 296                  // persistent, 2 CTAs/SM

// ---------------------------------------------------------------------------
// Scratch (__device__ globals; allocation-free rule)
// ---------------------------------------------------------------------------
__device__ __align__(16) unsigned char g_Xsb[NT * TILE_BYTES]; // swizzled bf16 tiles (4 MB, L2-resident)
__device__ float g_sq[NN];
__device__ double g_num, g_den;
__device__ unsigned g_ctr;

__device__ __forceinline__ unsigned smem_u32(const void* p) {
    unsigned a;
    asm("{ .reg .u64 t; cvta.to.shared.u64 t, %1; cvt.u32.u64 %0, t; }" : "=r"(a) : "l"(p));
    return a;
}

// m16n8k16 bf16 MMA, D += A*B (fp32 acc)
__device__ __forceinline__ void mma16816(float* d, const unsigned* a, const unsigned* b) {
    asm volatile(
        "mma.sync.aligned.m16n8k16.row.col.f32.bf16.bf16.f32 "
        "{%0,%1,%2,%3}, {%4,%5,%6,%7}, {%8,%9}, {%0,%1,%2,%3};"
        : "+f"(d[0]), "+f"(d[1]), "+f"(d[2]), "+f"(d[3])
        : "r"(a[0]), "r"(a[1]), "r"(a[2]), "r"(a[3]), "r"(b[0]), "r"(b[1]));
}
__device__ __forceinline__ void ldsm_x4(unsigned* r, unsigned addr) {
    asm volatile("ldmatrix.sync.aligned.m8n8.x4.shared.b16 {%0,%1,%2,%3}, [%4];"
                 : "=r"(r[0]), "=r"(r[1]), "=r"(r[2]), "=r"(r[3]) : "r"(addr));
}
__device__ __forceinline__ void cp16(unsigned sdst, const void* gsrc) {
    asm volatile("cp.async.cg.shared.global [%0], [%1], 16;" :: "r"(sdst), "l"(gsrc) : "memory");
}
__device__ __forceinline__ void decode_pair(int t, int& bi, int& bj) {
    int rem = t; bi = 0;
    while (rem >= NT - bi) { rem -= NT - bi; bi++; }
    bj = bi + rem;
}

// ---------------------------------------------------------------------------
// Prep: Xs = X*sqrt(params) -> bf16, per-tile 8-row XOR swizzle
//   element (row,e): byte = row*128 + (((e>>3) ^ (row&7))<<4) + (e&7)*2
// One thread per 16 elements (quarter row); swizzle groups are 16B-aligned,
// so stores are two uint4. sq[i] = ||Xs_i||^2 exact fp32 (4-thread shuffle).
// Also resets the global accumulators + completion counter.
// ---------------------------------------------------------------------------
__global__ void prep_kernel(const float* __restrict__ X,
                            const float* __restrict__ params) {
    if (blockIdx.x == 0 && threadIdx.x == 0) { g_num = 0.0; g_den = 0.0; g_ctr = 0u; }
    const int g   = blockIdx.x * blockDim.x + threadIdx.x;  // 0..32767
    const int row = g >> 2;
    const int q   = g & 3;

    const float4* P4 = (const float4*)params;          // 16 float4, L1 broadcast
    const float4* X4 = (const float4*)(X + row * DD + q * 16);

    float s = 0.0f;
    unsigned pk[8];
    #pragma unroll
    for (int i = 0; i < 4; i++) {
        float4 p = P4[q * 4 + i];
        float4 x = X4[i];
        float a = x.x * sqrtf(p.x);
        float b = x.y * sqrtf(p.y);
        float c = x.z * sqrtf(p.z);
        float d = x.w * sqrtf(p.w);
        s += a * a + b * b + c * c + d * d;
        __nv_bfloat162 lo = __float22bfloat162_rn(make_float2(a, b));
        __nv_bfloat162 hi = __float22bfloat162_rn(make_float2(c, d));
        pk[i * 2]     = *(unsigned*)&lo;
        pk[i * 2 + 1] = *(unsigned*)&hi;
    }

    const int tile = row >> 7, ri = row & 127;
    unsigned char* tb = g_Xsb + (size_t)tile * TILE_BYTES;
    const unsigned e8a = (unsigned)(q * 2), e8b = e8a + 1;
    *(uint4*)(tb + ri * 128 + ((e8a ^ (unsigned)(ri & 7)) << 4)) =
        make_uint4(pk[0], pk[1], pk[2], pk[3]);
    *(uint4*)(tb + ri * 128 + ((e8b ^ (unsigned)(ri & 7)) << 4)) =
        make_uint4(pk[4], pk[5], pk[6], pk[7]);

    s += __shfl_xor_sync(0xFFFFFFFFu, s, 1);
    s += __shfl_xor_sync(0xFFFFFFFFu, s, 2);
    if (q == 0) g_sq[row] = s;
}

// ---------------------------------------------------------------------------
// Persistent HMMA tile kernel, cp.async double-buffered:
// per iter: issue next pair's LDGSTS into buf^1, wait current buf, compute
// (4x4 m16n8k16 atoms per warp, fused exp + reductions). Last CTA writes out.
// ---------------------------------------------------------------------------
__global__ __launch_bounds__(256, 2)
void tile_kernel(const float* __restrict__ target, float* __restrict__ out) {
    extern __shared__ __align__(16) unsigned char smem[];  // 2 x (A 16KB | B 16KB)

    const int tid  = threadIdx.x;
    const int wid  = tid >> 5;
    const int lane = tid & 31;
    const int wr   = wid >> 2;     // row block of 64
    const int wc   = wid & 3;      // col block of 32
    const int gid  = lane >> 2;
    const int tig  = lane & 3;

    const int l7    = lane & 7;
    const int a_row = 64 * wr + 8 * ((lane >> 3) & 1) + l7;
    const int a_cp  = lane >> 4;
    const int b_row = 32 * wc + 8 * (lane >> 4) + l7;
    const int b_cp  = (lane >> 3) & 1;

    const unsigned sbase = smem_u32(smem);

    float ln = 0.0f, ld = 0.0f;
    unsigned pb = 0;

    int t = blockIdx.x;
    int bi, bj;
    decode_pair(t, bi, bj);
    // prologue: stage first pair into buf 0
    {
        const unsigned char* gA = g_Xsb + (size_t)bi * TILE_BYTES;
        const unsigned char* gB = g_Xsb + (size_t)bj * TILE_BYTES;
        #pragma unroll
        for (int s = 0; s < 4; s++) {
            int c = (tid + 256 * s) * 16;
            cp16(sbase + c, gA + c);
            cp16(sbase + TILE_BYTES + c, gB + c);
        }
        asm volatile("cp.async.commit_group;" ::: "memory");
    }

    for (; t < NPAIRS; t += GRID_TILE) {
        const int tn = t + GRID_TILE;
        int nbi = 0, nbj = 0;
        if (tn < NPAIRS) {
            decode_pair(tn, nbi, nbj);
            const unsigned nb = sbase + (pb ^ 1) * BUF_BYTES;
            const unsigned char* gA = g_Xsb + (size_t)nbi * TILE_BYTES;
            const unsigned char* gB = g_Xsb + (size_t)nbj * TILE_BYTES;
            #pragma unroll
            for (int s = 0; s < 4; s++) {
                int c = (tid + 256 * s) * 16;
                cp16(nb + c, gA + c);
                cp16(nb + TILE_BYTES + c, gB + c);
            }
        }
        asm volatile("cp.async.commit_group;" ::: "memory");
        asm volatile("cp.async.wait_group 1;" ::: "memory");  // current buf ready
        __syncthreads();

        const unsigned sA = sbase + pb * BUF_BYTES;
        const unsigned sB = sA + TILE_BYTES;

        // ---- MMA mainloop: K=64 as 4 steps of 16 ----
        float acc[4][4][4];
        #pragma unroll
        for (int ra = 0; ra < 4; ra++)
            #pragma unroll
            for (int ca = 0; ca < 4; ca++)
                #pragma unroll
                for (int qq = 0; qq < 4; qq++) acc[ra][ca][qq] = 0.0f;

        #pragma unroll
        for (int ks = 0; ks < 4; ks++) {
            const unsigned axor = (((unsigned)(2 * ks + a_cp)) ^ (unsigned)l7) << 4;
            const unsigned bxor = (((unsigned)(2 * ks + b_cp)) ^ (unsigned)l7) << 4;

            unsigned a[4][4];
            #pragma unroll
            for (int ra = 0; ra < 4; ra++)
                ldsm_x4(a[ra], sA + (unsigned)(a_row + 16 * ra) * 128 + axor);
            unsigned b[2][4];
            #pragma unroll
            for (int cb = 0; cb < 2; cb++)
                ldsm_x4(b[cb], sB + (unsigned)(b_row + 16 * cb) * 128 + bxor);

            #pragma unroll
            for (int ra = 0; ra < 4; ra++)
                #pragma unroll
                for (int ca = 0; ca < 4; ca++)
                    mma16816(acc[ra][ca], a[ra], &b[ca >> 1][(ca & 1) * 2]);
        }

        // ---- epilogue scalars: direct LDG (g_sq/target are L1/L2-resident) ----
        float sqjv[8], tjv[8];
        #pragma unroll
        for (int ca = 0; ca < 4; ca++) {
            const int cg = bj * TILE + 32 * wc + 8 * ca + 2 * tig;
            sqjv[2 * ca]     = __ldg(g_sq + cg);
            sqjv[2 * ca + 1] = __ldg(g_sq + cg + 1);
            tjv[2 * ca]      = __ldg(target + cg);
            tjv[2 * ca + 1]  = __ldg(target + cg + 1);
        }

        // ---- fused epilogue: exp + both reductions, all in registers ----
        const bool diag = (bi == bj);
        #pragma unroll
        for (int ra = 0; ra < 4; ra++) {
            const int r0 = 64 * wr + 16 * ra + gid;
            const int r1 = r0 + 8;
            const float sqi0 = __ldg(g_sq + bi * TILE + r0);
            const float sqi1 = __ldg(g_sq + bi * TILE + r1);
            const float ti0  = __ldg(target + bi * TILE + r0);
            const float ti1  = __ldg(target + bi * TILE + r1);
            float rn0 = 0.0f, rn1 = 0.0f, rd = 0.0f;
            #pragma unroll
            for (int ca = 0; ca < 4; ca++) {
                const int c0 = 32 * wc + 8 * ca + 2 * tig;
                const float* d = acc[ra][ca];
                float K00 = __expf(-fmaxf(sqi0 + sqjv[2*ca]   - 2.0f * d[0], 0.0f));
                float K01 = __expf(-fmaxf(sqi0 + sqjv[2*ca+1] - 2.0f * d[1], 0.0f));
                float K10 = __expf(-fmaxf(sqi1 + sqjv[2*ca]   - 2.0f * d[2], 0.0f));
                float K11 = __expf(-fmaxf(sqi1 + sqjv[2*ca+1] - 2.0f * d[3], 0.0f));
                if (diag) {   // reference keeps eye() on the diagonal
                    if (r0 == c0)     K00 = 1.0f;
                    if (r0 == c0 + 1) K01 = 1.0f;
                    if (r1 == c0)     K10 = 1.0f;
                    if (r1 == c0 + 1) K11 = 1.0f;
                }
                rn0 = fmaf(tjv[2*ca], K00, rn0); rn0 = fmaf(tjv[2*ca+1], K01, rn0);
                rn1 = fmaf(tjv[2*ca], K10, rn1); rn1 = fmaf(tjv[2*ca+1], K11, rn1);
                rd  = fmaf(K00, K00, rd); rd = fmaf(K01, K01, rd);
                rd  = fmaf(K10, K10, rd); rd = fmaf(K11, K11, rd);
            }
            const float w = diag ? 1.0f : 2.0f;  // symmetry: off-diag pairs x2
            ln = fmaf(w * ti0, rn0, ln);
            ln = fmaf(w * ti1, rn1, ln);
            ld = fmaf(w, rd, ld);
        }

        __syncthreads();   // reads of buf[pb] done before it is re-staged
        pb ^= 1;
        bi = nbi; bj = nbj;
    }

    // block reduction -> double atomics; last CTA computes the final scalar
    #pragma unroll
    for (int o = 16; o; o >>= 1) {
        ln += __shfl_xor_sync(0xFFFFFFFFu, ln, o);
        ld += __shfl_xor_sync(0xFFFFFFFFu, ld, o);
    }
    __shared__ float rn_[8], rd_[8];
    if (lane == 0) { rn_[wid] = ln; rd_[wid] = ld; }
    __syncthreads();
    if (tid == 0) {
        float a = 0.0f, b = 0.0f;
        #pragma unroll
        for (int k = 0; k < 8; k++) { a += rn_[k]; b += rd_[k]; }
        atomicAdd(&g_num, (double)a);
        atomicAdd(&g_den, (double)b);
        __threadfence();
        const unsigned done = atomicAdd(&g_ctr, 1u);
        if (done == GRID_TILE - 1) {
            const double num = *(volatile double*)&g_num;
            const double den = *(volatile double*)&g_den;
            out[0] = (float)(-num / ((double)NN * sqrt(den)));
        }
    }
}

extern "C" void kernel_launch(void* const* d_in, const int* in_sizes, int n_in,
                              void* d_out, int out_size) {
    const float* X      = (const float*)d_in[0];
    const float* target = (const float*)d_in[1];
    const float* params = (const float*)d_in[2];
    float* out = (float*)d_out;

    cudaFuncSetAttribute(tile_kernel,
                         cudaFuncAttributeMaxDynamicSharedMemorySize, 2 * BUF_BYTES);

    prep_kernel<<<128, 256>>>(X, params);
    tile_kernel<<<GRID_TILE, 256, 2 * BUF_BYTES>>>(target, out);
}

// round 12
// speedup vs baseline: 4.4507x; 1.1302x over previous
#include <cuda_runtime.h>
#include <cuda_bf16.h>
#include <cuda_fp16.h>
#include <math.h>

#define NN 8192
#define DD 64
#define TILE 128
#define NT (NN / TILE)                 // 64 tiles per dim
#define NPAIRS (NT * (NT + 1) / 2)     // 2080 triangular tile pairs
#define TILE_BYTES (TILE * DD * 2)     // 16 KB: 128 rows x 64 bf16 (128 B/row)
#define BUF_BYTES (2 * TILE_BYTES)     // A + B per stage
#define GRID_TILE 296                  // persistent, 2 CTAs/SM
#define NLOG2E (-1.4426950408889634f)  // -log2(e)
#define TWOLOG2E 2.8853900817779268f   //  2*log2(e)

// ---------------------------------------------------------------------------
// Scratch (__device__ globals; allocation-free rule)
// ---------------------------------------------------------------------------
__device__ __align__(16) unsigned char g_Xsb[NT * TILE_BYTES]; // swizzled bf16 tiles (4 MB, L2-resident)
__device__ float g_sq2[NN];            // -log2e * ||Xs_i||^2 (pre-scaled exp2 bias)
__device__ __half g_th[NN];            // target in fp16 (for packed reductions)
__device__ double g_num, g_den;
__device__ unsigned g_ctr;

__device__ __forceinline__ unsigned smem_u32(const void* p) {
    unsigned a;
    asm("{ .reg .u64 t; cvta.to.shared.u64 t, %1; cvt.u32.u64 %0, t; }" : "=r"(a) : "l"(p));
    return a;
}
__device__ __forceinline__ void mma16816(float* d, const unsigned* a, const unsigned* b) {
    asm volatile(
        "mma.sync.aligned.m16n8k16.row.col.f32.bf16.bf16.f32 "
        "{%0,%1,%2,%3}, {%4,%5,%6,%7}, {%8,%9}, {%0,%1,%2,%3};"
        : "+f"(d[0]), "+f"(d[1]), "+f"(d[2]), "+f"(d[3])
        : "r"(a[0]), "r"(a[1]), "r"(a[2]), "r"(a[3]), "r"(b[0]), "r"(b[1]));
}
__device__ __forceinline__ void ldsm_x4(unsigned* r, unsigned addr) {
    asm volatile("ldmatrix.sync.aligned.m8n8.x4.shared.b16 {%0,%1,%2,%3}, [%4];"
                 : "=r"(r[0]), "=r"(r[1]), "=r"(r[2]), "=r"(r[3]) : "r"(addr));
}
__device__ __forceinline__ void cp16(unsigned sdst, const void* gsrc) {
    asm volatile("cp.async.cg.shared.global [%0], [%1], 16;" :: "r"(sdst), "l"(gsrc) : "memory");
}
// triangular row start: off(bi) = bi*NT - bi*(bi-1)/2
__device__ __forceinline__ int tri_off(int bi) { return bi * NT - (bi * (bi - 1)) / 2; }
__device__ __forceinline__ void decode_pair(int t, int& bi, int& bj) {
    // closed form + fixup (fp32 sqrt can be off by 1 at boundaries)
    int b = (int)((2.0f * NT + 1.0f
                   - sqrtf(fmaxf((2.0f * NT + 1.0f) * (2.0f * NT + 1.0f) - 8.0f * (float)t, 0.0f)))
                  * 0.5f);
    if (b < 0) b = 0; if (b > NT - 1) b = NT - 1;
    while (b + 1 <= NT - 1 && tri_off(b + 1) <= t) b++;
    while (tri_off(b) > t) b--;
    bi = b;
    bj = b + (t - tri_off(b));
}

// ---------------------------------------------------------------------------
// Prep: Xs = X*sqrt(params) -> bf16, per-tile 8-row XOR swizzle.
// g_sq2[i] = -log2e*||Xs_i||^2 ; g_th[i] = half(target[i]).
// One thread per 16 elements (quarter row).
// ---------------------------------------------------------------------------
__global__ void prep_kernel(const float* __restrict__ X,
                            const float* __restrict__ params,
                            const float* __restrict__ target) {
    if (blockIdx.x == 0 && threadIdx.x == 0) { g_num = 0.0; g_den = 0.0; g_ctr = 0u; }
    const int g   = blockIdx.x * blockDim.x + threadIdx.x;  // 0..32767
    const int row = g >> 2;
    const int q   = g & 3;

    const float4* P4 = (const float4*)params;
    const float4* X4 = (const float4*)(X + row * DD + q * 16);

    float s = 0.0f;
    unsigned pk[8];
    #pragma unroll
    for (int i = 0; i < 4; i++) {
        float4 p = P4[q * 4 + i];
        float4 x = X4[i];
        float a = x.x * sqrtf(p.x);
        float b = x.y * sqrtf(p.y);
        float c = x.z * sqrtf(p.z);
        float d = x.w * sqrtf(p.w);
        s += a * a + b * b + c * c + d * d;
        __nv_bfloat162 lo = __float22bfloat162_rn(make_float2(a, b));
        __nv_bfloat162 hi = __float22bfloat162_rn(make_float2(c, d));
        pk[i * 2]     = *(unsigned*)&lo;
        pk[i * 2 + 1] = *(unsigned*)&hi;
    }

    const int tile = row >> 7, ri = row & 127;
    unsigned char* tb = g_Xsb + (size_t)tile * TILE_BYTES;
    const unsigned e8a = (unsigned)(q * 2), e8b = e8a + 1;
    *(uint4*)(tb + ri * 128 + ((e8a ^ (unsigned)(ri & 7)) << 4)) =
        make_uint4(pk[0], pk[1], pk[2], pk[3]);
    *(uint4*)(tb + ri * 128 + ((e8b ^ (unsigned)(ri & 7)) << 4)) =
        make_uint4(pk[4], pk[5], pk[6], pk[7]);

    s += __shfl_xor_sync(0xFFFFFFFFu, s, 1);
    s += __shfl_xor_sync(0xFFFFFFFFu, s, 2);
    if (q == 0) {
        g_sq2[row] = NLOG2E * s;
        g_th[row]  = __float2half(target[row]);
    }
}

// ---------------------------------------------------------------------------
// Persistent HMMA tile kernel, cp.async double-buffered, packed-fp16 epilogue.
// K_ij = exp2(sq2_i + sq2_j + 2log2e*dot)  (== exp(-d2)); off-diag K under-
// flows to 0 in fp16 (contributes < fp32 ulp); diagonal forced to exactly 1.
// ---------------------------------------------------------------------------
__global__ __launch_bounds__(256, 2)
void tile_kernel(const float* __restrict__ target, float* __restrict__ out) {
    extern __shared__ __align__(16) unsigned char smem[];  // 2 x (A 16KB | B 16KB)

    const int tid  = threadIdx.x;
    const int wid  = tid >> 5;
    const int lane = tid & 31;
    const int wr   = wid >> 2;
    const int wc   = wid & 3;
    const int gid  = lane >> 2;
    const int tig  = lane & 3;

    const int l7    = lane & 7;
    const int a_row = 64 * wr + 8 * ((lane >> 3) & 1) + l7;
    const int a_cp  = lane >> 4;
    const int b_row = 32 * wc + 8 * (lane >> 4) + l7;
    const int b_cp  = (lane >> 3) & 1;

    const unsigned sbase = smem_u32(smem);
    const __half hone = __float2half(1.0f);

    float ln = 0.0f, ld = 0.0f;
    unsigned pb = 0;

    int t = blockIdx.x;
    int bi, bj;
    decode_pair(t, bi, bj);
    {   // prologue: stage first pair into buf 0
        const unsigned char* gA = g_Xsb + (size_t)bi * TILE_BYTES;
        const unsigned char* gB = g_Xsb + (size_t)bj * TILE_BYTES;
        #pragma unroll
        for (int s = 0; s < 4; s++) {
            int c = (tid + 256 * s) * 16;
            cp16(sbase + c, gA + c);
            cp16(sbase + TILE_BYTES + c, gB + c);
        }
        asm volatile("cp.async.commit_group;" ::: "memory");
    }

    for (; t < NPAIRS; t += GRID_TILE) {
        const int tnx = t + GRID_TILE;
        int nbi = 0, nbj = 0;
        if (tnx < NPAIRS) {
            decode_pair(tnx, nbi, nbj);
            const unsigned nb = sbase + (pb ^ 1) * BUF_BYTES;
            const unsigned char* gA = g_Xsb + (size_t)nbi * TILE_BYTES;
            const unsigned char* gB = g_Xsb + (size_t)nbj * TILE_BYTES;
            #pragma unroll
            for (int s = 0; s < 4; s++) {
                int c = (tid + 256 * s) * 16;
                cp16(nb + c, gA + c);
                cp16(nb + TILE_BYTES + c, gB + c);
            }
        }
        asm volatile("cp.async.commit_group;" ::: "memory");
        asm volatile("cp.async.wait_group 1;" ::: "memory");
        __syncthreads();

        const unsigned sA = sbase + pb * BUF_BYTES;
        const unsigned sB = sA + TILE_BYTES;

        // ---- MMA mainloop: K=64 as 4 steps of 16 ----
        float acc[4][4][4];
        #pragma unroll
        for (int ra = 0; ra < 4; ra++)
            #pragma unroll
            for (int ca = 0; ca < 4; ca++)
                #pragma unroll
                for (int qq = 0; qq < 4; qq++) acc[ra][ca][qq] = 0.0f;

        #pragma unroll
        for (int ks = 0; ks < 4; ks++) {
            const unsigned axor = (((unsigned)(2 * ks + a_cp)) ^ (unsigned)l7) << 4;
            const unsigned bxor = (((unsigned)(2 * ks + b_cp)) ^ (unsigned)l7) << 4;
            unsigned a[4][4];
            #pragma unroll
            for (int ra = 0; ra < 4; ra++)
                ldsm_x4(a[ra], sA + (unsigned)(a_row + 16 * ra) * 128 + axor);
            unsigned b[2][4];
            #pragma unroll
            for (int cb = 0; cb < 2; cb++)
                ldsm_x4(b[cb], sB + (unsigned)(b_row + 16 * cb) * 128 + bxor);
            #pragma unroll
            for (int ra = 0; ra < 4; ra++)
                #pragma unroll
                for (int ca = 0; ca < 4; ca++)
                    mma16816(acc[ra][ca], a[ra], &b[ca >> 1][(ca & 1) * 2]);
        }

        // ---- per-column scalars (L1/L2-resident) ----
        float sqjv[8];
        __half2 tj2[4];
        #pragma unroll
        for (int ca = 0; ca < 4; ca++) {
            const int cg = bj * TILE + 32 * wc + 8 * ca + 2 * tig;
            sqjv[2 * ca]     = __ldg(g_sq2 + cg);
            sqjv[2 * ca + 1] = __ldg(g_sq2 + cg + 1);
            tj2[ca]          = *(const __half2*)(g_th + cg);   // aligned (cg even)
        }

        // ---- packed fp16x2 epilogue: exp2 + both reductions ----
        const bool diag = (bi == bj);
        float tn = 0.0f;
        __half2 rd2 = __float2half2_rn(0.0f);
        #pragma unroll
        for (int ra = 0; ra < 4; ra++) {
            const int r0 = 64 * wr + 16 * ra + gid;
            const int r1 = r0 + 8;
            const float sqi0 = __ldg(g_sq2 + bi * TILE + r0);
            const float sqi1 = __ldg(g_sq2 + bi * TILE + r1);
            const float ti0  = __ldg(target + bi * TILE + r0);
            const float ti1  = __ldg(target + bi * TILE + r1);
            __half2 rn0 = __float2half2_rn(0.0f);
            __half2 rn1 = __float2half2_rn(0.0f);
            #pragma unroll
            for (int ca = 0; ca < 4; ca++) {
                const float* d = acc[ra][ca];
                const float a00 = fmaf(d[0], TWOLOG2E, sqi0 + sqjv[2 * ca]);
                const float a01 = fmaf(d[1], TWOLOG2E, sqi0 + sqjv[2 * ca + 1]);
                const float a10 = fmaf(d[2], TWOLOG2E, sqi1 + sqjv[2 * ca]);
                const float a11 = fmaf(d[3], TWOLOG2E, sqi1 + sqjv[2 * ca + 1]);
                __half2 k0 = h2exp2(__floats2half2_rn(a00, a01));  // ex2.approx.f16x2
                __half2 k1 = h2exp2(__floats2half2_rn(a10, a11));
                if (diag) {   // reference keeps eye() on the diagonal
                    const int c0 = 32 * wc + 8 * ca + 2 * tig;
                    if (r0 == c0)     k0 = __halves2half2(hone, __high2half(k0));
                    if (r0 == c0 + 1) k0 = __halves2half2(__low2half(k0), hone);
                    if (r1 == c0)     k1 = __halves2half2(hone, __high2half(k1));
                    if (r1 == c0 + 1) k1 = __halves2half2(__low2half(k1), hone);
                }
                rn0 = __hfma2(tj2[ca], k0, rn0);
                rn1 = __hfma2(tj2[ca], k1, rn1);
                rd2 = __hfma2(k0, k0, rd2);
                rd2 = __hfma2(k1, k1, rd2);
            }
            const float2 f0 = __half22float2(rn0);
            const float2 f1 = __half22float2(rn1);
            tn = fmaf(ti0, f0.x + f0.y, tn);
            tn = fmaf(ti1, f1.x + f1.y, tn);
        }
        const float w = diag ? 1.0f : 2.0f;   // symmetry: off-diag pairs x2
        const float2 fd = __half22float2(rd2);
        ln = fmaf(w, tn, ln);
        ld = fmaf(w, fd.x + fd.y, ld);

        __syncthreads();   // reads of buf[pb] done before restage
        pb ^= 1;
        bi = nbi; bj = nbj;
    }

    // block reduction -> double atomics; last CTA writes the final scalar
    #pragma unroll
    for (int o = 16; o; o >>= 1) {
        ln += __shfl_xor_sync(0xFFFFFFFFu, ln, o);
        ld += __shfl_xor_sync(0xFFFFFFFFu, ld, o);
    }
    __shared__ float rn_[8], rd_[8];
    if (lane == 0) { rn_[wid] = ln; rd_[wid] = ld; }
    __syncthreads();
    if (tid == 0) {
        float a = 0.0f, b = 0.0f;
        #pragma unroll
        for (int k = 0; k < 8; k++) { a += rn_[k]; b += rd_[k]; }
        atomicAdd(&g_num, (double)a);
        atomicAdd(&g_den, (double)b);
        __threadfence();
        const unsigned done = atomicAdd(&g_ctr, 1u);
        if (done == GRID_TILE - 1) {
            const double num = *(volatile double*)&g_num;
            const double den = *(volatile double*)&g_den;
            out[0] = (float)(-num / ((double)NN * sqrt(den)));
        }
    }
}

extern "C" void kernel_launch(void* const* d_in, const int* in_sizes, int n_in,
                              void* d_out, int out_size) {
    const float* X      = (const float*)d_in[0];
    const float* target = (const float*)d_in[1];
    const float* params = (const float*)d_in[2];
    float* out = (float*)d_out;

    cudaFuncSetAttribute(tile_kernel,
                         cudaFuncAttributeMaxDynamicSharedMemorySize, 2 * BUF_BYTES);

    prep_kernel<<<128, 256>>>(X, params, target);
    tile_kernel<<<GRID_TILE, 256, 2 * BUF_BYTES>>>(target, out);
}

// round 13
// speedup vs baseline: 4.7606x; 1.0696x over previous
#include <cuda_runtime.h>
#include <cuda_bf16.h>
#include <cuda_fp16.h>
#include <math.h>

#define NN 8192
#define DD 64
#define TILE 128
#define NT (NN / TILE)                 // 64 tiles per dim
#define NPAIRS (NT * (NT + 1) / 2)     // 2080 triangular tile pairs
#define TILE_BYTES (TILE * DD * 2)     // 16 KB: 128 rows x 64 bf16 (128 B/row)
#define BUF_BYTES (2 * TILE_BYTES)     // A + B per stage
#define GRID_TILE 296                  // persistent, 2 CTAs/SM
#define NLOG2E (-1.4426950408889634f)  // -log2(e)
#define TWOLOG2E 2.8853900817779268f   //  2*log2(e)
#define SKIP_THR (-25.0f)              // exp2(arg) < 2^-25 -> fp16 flushes to ~0 anyway

// ---------------------------------------------------------------------------
// Scratch (__device__ globals; allocation-free rule)
// ---------------------------------------------------------------------------
__device__ __align__(16) unsigned char g_Xsb[NT * TILE_BYTES]; // swizzled bf16 tiles (4 MB, L2-resident)
__device__ float g_sq2[NN];            // -log2e * ||Xs_i||^2 (pre-scaled exp2 bias)
__device__ __half g_th[NN];            // target in fp16 (for packed reductions)
__device__ double g_num, g_den;
__device__ unsigned g_ctr;

__device__ __forceinline__ unsigned smem_u32(const void* p) {
    unsigned a;
    asm("{ .reg .u64 t; cvta.to.shared.u64 t, %1; cvt.u32.u64 %0, t; }" : "=r"(a) : "l"(p));
    return a;
}
__device__ __forceinline__ void mma16816(float* d, const unsigned* a, const unsigned* b) {
    asm volatile(
        "mma.sync.aligned.m16n8k16.row.col.f32.bf16.bf16.f32 "
        "{%0,%1,%2,%3}, {%4,%5,%6,%7}, {%8,%9}, {%0,%1,%2,%3};"
        : "+f"(d[0]), "+f"(d[1]), "+f"(d[2]), "+f"(d[3])
        : "r"(a[0]), "r"(a[1]), "r"(a[2]), "r"(a[3]), "r"(b[0]), "r"(b[1]));
}
__device__ __forceinline__ void ldsm_x4(unsigned* r, unsigned addr) {
    asm volatile("ldmatrix.sync.aligned.m8n8.x4.shared.b16 {%0,%1,%2,%3}, [%4];"
                 : "=r"(r[0]), "=r"(r[1]), "=r"(r[2]), "=r"(r[3]) : "r"(addr));
}
__device__ __forceinline__ void cp16(unsigned sdst, const void* gsrc) {
    asm volatile("cp.async.cg.shared.global [%0], [%1], 16;" :: "r"(sdst), "l"(gsrc) : "memory");
}
__device__ __forceinline__ int tri_off(int bi) { return bi * NT - (bi * (bi - 1)) / 2; }
__device__ __forceinline__ void decode_pair(int t, int& bi, int& bj) {
    int b = (int)((2.0f * NT + 1.0f
                   - sqrtf(fmaxf((2.0f * NT + 1.0f) * (2.0f * NT + 1.0f) - 8.0f * (float)t, 0.0f)))
                  * 0.5f);
    if (b < 0) b = 0; if (b > NT - 1) b = NT - 1;
    while (b + 1 <= NT - 1 && tri_off(b + 1) <= t) b++;
    while (tri_off(b) > t) b--;
    bi = b;
    bj = b + (t - tri_off(b));
}

// ---------------------------------------------------------------------------
// Prep: Xs = X*sqrt(params) -> bf16, per-tile 8-row XOR swizzle.
// g_sq2[i] = -log2e*||Xs_i||^2 ; g_th[i] = half(target[i]).
// ---------------------------------------------------------------------------
__global__ void prep_kernel(const float* __restrict__ X,
                            const float* __restrict__ params,
                            const float* __restrict__ target) {
    if (blockIdx.x == 0 && threadIdx.x == 0) { g_num = 0.0; g_den = 0.0; g_ctr = 0u; }
    const int g   = blockIdx.x * blockDim.x + threadIdx.x;  // 0..32767
    const int row = g >> 2;
    const int q   = g & 3;

    const float4* P4 = (const float4*)params;
    const float4* X4 = (const float4*)(X + row * DD + q * 16);

    float s = 0.0f;
    unsigned pk[8];
    #pragma unroll
    for (int i = 0; i < 4; i++) {
        float4 p = P4[q * 4 + i];
        float4 x = X4[i];
        float a = x.x * sqrtf(p.x);
        float b = x.y * sqrtf(p.y);
        float c = x.z * sqrtf(p.z);
        float d = x.w * sqrtf(p.w);
        s += a * a + b * b + c * c + d * d;
        __nv_bfloat162 lo = __float22bfloat162_rn(make_float2(a, b));
        __nv_bfloat162 hi = __float22bfloat162_rn(make_float2(c, d));
        pk[i * 2]     = *(unsigned*)&lo;
        pk[i * 2 + 1] = *(unsigned*)&hi;
    }

    const int tile = row >> 7, ri = row & 127;
    unsigned char* tb = g_Xsb + (size_t)tile * TILE_BYTES;
    const unsigned e8a = (unsigned)(q * 2), e8b = e8a + 1;
    *(uint4*)(tb + ri * 128 + ((e8a ^ (unsigned)(ri & 7)) << 4)) =
        make_uint4(pk[0], pk[1], pk[2], pk[3]);
    *(uint4*)(tb + ri * 128 + ((e8b ^ (unsigned)(ri & 7)) << 4)) =
        make_uint4(pk[4], pk[5], pk[6], pk[7]);

    s += __shfl_xor_sync(0xFFFFFFFFu, s, 1);
    s += __shfl_xor_sync(0xFFFFFFFFu, s, 2);
    if (q == 0) {
        g_sq2[row] = NLOG2E * s;
        g_th[row]  = __float2half(target[row]);
    }
}

// ---------------------------------------------------------------------------
// Persistent HMMA tile kernel, cp.async double-buffered.
// Epilogue: compute exp2 args (fp32, from MMA dot) for every element; warp-
// vote skip of the exp+reduction block when all 4 args < SKIP_THR (those K
// underflow to ~0 in the fp16 pipeline anyway -> numerically identical).
// Diagonal tiles take the full path with eye() forcing.
// ---------------------------------------------------------------------------
__global__ __launch_bounds__(256, 2)
void tile_kernel(const float* __restrict__ target, float* __restrict__ out) {
    extern __shared__ __align__(16) unsigned char smem[];  // 2 x (A 16KB | B 16KB)

    const int tid  = threadIdx.x;
    const int wid  = tid >> 5;
    const int lane = tid & 31;
    const int wr   = wid >> 2;
    const int wc   = wid & 3;
    const int gid  = lane >> 2;
    const int tig  = lane & 3;

    const int l7    = lane & 7;
    const int a_row = 64 * wr + 8 * ((lane >> 3) & 1) + l7;
    const int a_cp  = lane >> 4;
    const int b_row = 32 * wc + 8 * (lane >> 4) + l7;
    const int b_cp  = (lane >> 3) & 1;

    const unsigned sbase = smem_u32(smem);
    const __half hone = __float2half(1.0f);

    float ln = 0.0f, ld = 0.0f;
    unsigned pb = 0;

    int t = blockIdx.x;
    int bi, bj;
    decode_pair(t, bi, bj);
    {   // prologue: stage first pair into buf 0
        const unsigned char* gA = g_Xsb + (size_t)bi * TILE_BYTES;
        const unsigned char* gB = g_Xsb + (size_t)bj * TILE_BYTES;
        #pragma unroll
        for (int s = 0; s < 4; s++) {
            int c = (tid + 256 * s) * 16;
            cp16(sbase + c, gA + c);
            cp16(sbase + TILE_BYTES + c, gB + c);
        }
        asm volatile("cp.async.commit_group;" ::: "memory");
    }

    for (; t < NPAIRS; t += GRID_TILE) {
        const int tnx = t + GRID_TILE;
        int nbi = 0, nbj = 0;
        if (tnx < NPAIRS) {
            decode_pair(tnx, nbi, nbj);
            const unsigned nb = sbase + (pb ^ 1) * BUF_BYTES;
            const unsigned char* gA = g_Xsb + (size_t)nbi * TILE_BYTES;
            const unsigned char* gB = g_Xsb + (size_t)nbj * TILE_BYTES;
            #pragma unroll
            for (int s = 0; s < 4; s++) {
                int c = (tid + 256 * s) * 16;
                cp16(nb + c, gA + c);
                cp16(nb + TILE_BYTES + c, gB + c);
            }
        }
        asm volatile("cp.async.commit_group;" ::: "memory");
        asm volatile("cp.async.wait_group 1;" ::: "memory");
        __syncthreads();

        const unsigned sA = sbase + pb * BUF_BYTES;
        const unsigned sB = sA + TILE_BYTES;

        // ---- MMA mainloop: K=64 as 4 steps of 16 ----
        float acc[4][4][4];
        #pragma unroll
        for (int ra = 0; ra < 4; ra++)
            #pragma unroll
            for (int ca = 0; ca < 4; ca++)
                #pragma unroll
                for (int qq = 0; qq < 4; qq++) acc[ra][ca][qq] = 0.0f;

        #pragma unroll
        for (int ks = 0; ks < 4; ks++) {
            const unsigned axor = (((unsigned)(2 * ks + a_cp)) ^ (unsigned)l7) << 4;
            const unsigned bxor = (((unsigned)(2 * ks + b_cp)) ^ (unsigned)l7) << 4;
            unsigned a[4][4];
            #pragma unroll
            for (int ra = 0; ra < 4; ra++)
                ldsm_x4(a[ra], sA + (unsigned)(a_row + 16 * ra) * 128 + axor);
            unsigned b[2][4];
            #pragma unroll
            for (int cb = 0; cb < 2; cb++)
                ldsm_x4(b[cb], sB + (unsigned)(b_row + 16 * cb) * 128 + bxor);
            #pragma unroll
            for (int ra = 0; ra < 4; ra++)
                #pragma unroll
                for (int ca = 0; ca < 4; ca++)
                    mma16816(acc[ra][ca], a[ra], &b[ca >> 1][(ca & 1) * 2]);
        }

        // ---- per-column scalars (L1/L2-resident) ----
        float sqjv[8];
        __half2 tj2[4];
        #pragma unroll
        for (int ca = 0; ca < 4; ca++) {
            const int cg = bj * TILE + 32 * wc + 8 * ca + 2 * tig;
            sqjv[2 * ca]     = __ldg(g_sq2 + cg);
            sqjv[2 * ca + 1] = __ldg(g_sq2 + cg + 1);
            tj2[ca]          = *(const __half2*)(g_th + cg);   // aligned (cg even)
        }

        const bool diag = (bi == bj);
        float tn = 0.0f;
        __half2 rd2 = __float2half2_rn(0.0f);

        if (!diag) {
            // ---- off-diag epilogue: args always, exp block behind warp vote ----
            #pragma unroll
            for (int ra = 0; ra < 4; ra++) {
                const int r0 = 64 * wr + 16 * ra + gid;
                const float sqi0 = __ldg(g_sq2 + bi * TILE + r0);
                const float sqi1 = __ldg(g_sq2 + bi * TILE + r0 + 8);
                const float ti0  = __ldg(target + bi * TILE + r0);
                const float ti1  = __ldg(target + bi * TILE + r0 + 8);
                __half2 rn0 = __float2half2_rn(0.0f);
                __half2 rn1 = __float2half2_rn(0.0f);
                #pragma unroll
                for (int ca = 0; ca < 4; ca++) {
                    const float* d = acc[ra][ca];
                    const float a00 = fmaf(d[0], TWOLOG2E, sqi0 + sqjv[2 * ca]);
                    const float a01 = fmaf(d[1], TWOLOG2E, sqi0 + sqjv[2 * ca + 1]);
                    const float a10 = fmaf(d[2], TWOLOG2E, sqi1 + sqjv[2 * ca]);
                    const float a11 = fmaf(d[3], TWOLOG2E, sqi1 + sqjv[2 * ca + 1]);
                    const float m = fmaxf(fmaxf(a00, a01), fmaxf(a10, a11));
                    if (__any_sync(0xFFFFFFFFu, m > SKIP_THR)) {
                        __half2 k0 = h2exp2(__floats2half2_rn(a00, a01));
                        __half2 k1 = h2exp2(__floats2half2_rn(a10, a11));
                        rn0 = __hfma2(tj2[ca], k0, rn0);
                        rn1 = __hfma2(tj2[ca], k1, rn1);
                        rd2 = __hfma2(k0, k0, rd2);
                        rd2 = __hfma2(k1, k1, rd2);
                    }
                }
                const float2 f0 = __half22float2(rn0);
                const float2 f1 = __half22float2(rn1);
                tn = fmaf(ti0, f0.x + f0.y, tn);
                tn = fmaf(ti1, f1.x + f1.y, tn);
            }
            ln = fmaf(2.0f, tn, ln);        // symmetry: off-diag pairs x2
            const float2 fd = __half22float2(rd2);
            ld = fmaf(2.0f, fd.x + fd.y, ld);
        } else {
            // ---- diagonal tile: full path with eye() forcing ----
            #pragma unroll
            for (int ra = 0; ra < 4; ra++) {
                const int r0 = 64 * wr + 16 * ra + gid;
                const int r1 = r0 + 8;
                const float sqi0 = __ldg(g_sq2 + bi * TILE + r0);
                const float sqi1 = __ldg(g_sq2 + bi * TILE + r1);
                const float ti0  = __ldg(target + bi * TILE + r0);
                const float ti1  = __ldg(target + bi * TILE + r1);
                __half2 rn0 = __float2half2_rn(0.0f);
                __half2 rn1 = __float2half2_rn(0.0f);
                #pragma unroll
                for (int ca = 0; ca < 4; ca++) {
                    const float* d = acc[ra][ca];
                    const float a00 = fmaf(d[0], TWOLOG2E, sqi0 + sqjv[2 * ca]);
                    const float a01 = fmaf(d[1], TWOLOG2E, sqi0 + sqjv[2 * ca + 1]);
                    const float a10 = fmaf(d[2], TWOLOG2E, sqi1 + sqjv[2 * ca]);
                    const float a11 = fmaf(d[3], TWOLOG2E, sqi1 + sqjv[2 * ca + 1]);
                    __half2 k0 = h2exp2(__floats2half2_rn(a00, a01));
                    __half2 k1 = h2exp2(__floats2half2_rn(a10, a11));
                    const int c0 = 32 * wc + 8 * ca + 2 * tig;
                    if (r0 == c0)     k0 = __halves2half2(hone, __high2half(k0));
                    if (r0 == c0 + 1) k0 = __halves2half2(__low2half(k0), hone);
                    if (r1 == c0)     k1 = __halves2half2(hone, __high2half(k1));
                    if (r1 == c0 + 1) k1 = __halves2half2(__low2half(k1), hone);
                    rn0 = __hfma2(tj2[ca], k0, rn0);
                    rn1 = __hfma2(tj2[ca], k1, rn1);
                    rd2 = __hfma2(k0, k0, rd2);
                    rd2 = __hfma2(k1, k1, rd2);
                }
                const float2 f0 = __half22float2(rn0);
                const float2 f1 = __half22float2(rn1);
                tn = fmaf(ti0, f0.x + f0.y, tn);
                tn = fmaf(ti1, f1.x + f1.y, tn);
            }
            ln += tn;
            const float2 fd = __half22float2(rd2);
            ld += fd.x + fd.y;
        }

        __syncthreads();   // reads of buf[pb] done before restage
        pb ^= 1;
        bi = nbi; bj = nbj;
    }

    // block reduction -> double atomics; last CTA writes the final scalar
    #pragma unroll
    for (int o = 16; o; o >>= 1) {
        ln += __shfl_xor_sync(0xFFFFFFFFu, ln, o);
        ld += __shfl_xor_sync(0xFFFFFFFFu, ld, o);
    }
    __shared__ float rn_[8], rd_[8];
    if (lane == 0) { rn_[wid] = ln; rd_[wid] = ld; }
    __syncthreads();
    if (tid == 0) {
        float a = 0.0f, b = 0.0f;
        #pragma unroll
        for (int k = 0; k < 8; k++) { a += rn_[k]; b += rd_[k]; }
        atomicAdd(&g_num, (double)a);
        atomicAdd(&g_den, (double)b);
        __threadfence();
        const unsigned done = atomicAdd(&g_ctr, 1u);
        if (done == GRID_TILE - 1) {
            const double num = *(volatile double*)&g_num;
            const double den = *(volatile double*)&g_den;
            out[0] = (float)(-num / ((double)NN * sqrt(den)));
        }
    }
}

extern "C" void kernel_launch(void* const* d_in, const int* in_sizes, int n_in,
                              void* d_out, int out_size) {
    const float* X      = (const float*)d_in[0];
    const float* target = (const float*)d_in[1];
    const float* params = (const float*)d_in[2];
    float* out = (float*)d_out;

    cudaFuncSetAttribute(tile_kernel,
                         cudaFuncAttributeMaxDynamicSharedMemorySize, 2 * BUF_BYTES);

    prep_kernel<<<128, 256>>>(X, params, target);
    tile_kernel<<<GRID_TILE, 256, 2 * BUF_BYTES>>>(target, out);
}

// round 14
// speedup vs baseline: 4.8024x; 1.0088x over previous
#include <cuda_runtime.h>
#include <cuda_bf16.h>
#include <cuda_fp16.h>
#include <math.h>

#define NN 8192
#define DD 64
#define TILE 128
#define NT (NN / TILE)                 // 64 tiles per dim
#define NPAIRS (NT * (NT + 1) / 2)     // 2080 triangular tile pairs
#define TILE_BYTES (TILE * DD * 2)     // 16 KB: 128 rows x 64 bf16 (128 B/row)
#define BUF_BYTES (2 * TILE_BYTES)     // A + B per stage
#define GRID_TILE 296                  // persistent, 2 CTAs/SM
#define NLOG2E (-1.4426950408889634f)  // -log2(e)
#define TWOLOG2E 2.8853900817779268f   //  2*log2(e)
#define SKIP_THR (-25.0f)              // exp2(arg) < 2^-25 -> fp16 flushes to ~0 anyway

// ---------------------------------------------------------------------------
// Scratch (__device__ globals; allocation-free rule)
// ---------------------------------------------------------------------------
__device__ __align__(16) unsigned char g_Xsb[NT * TILE_BYTES]; // swizzled bf16 tiles (4 MB, L2-resident)
__device__ float g_sq2[NN];            // -log2e * ||Xs_i||^2 (pre-scaled exp2 bias)
__device__ __half g_th[NN];            // target in fp16 (for packed reductions)
__device__ double g_num, g_den;
__device__ unsigned g_ctr;

__device__ __forceinline__ unsigned smem_u32(const void* p) {
    unsigned a;
    asm("{ .reg .u64 t; cvta.to.shared.u64 t, %1; cvt.u32.u64 %0, t; }" : "=r"(a) : "l"(p));
    return a;
}
__device__ __forceinline__ void mma16816(float* d, const unsigned* a, const unsigned* b) {
    asm volatile(
        "mma.sync.aligned.m16n8k16.row.col.f32.bf16.bf16.f32 "
        "{%0,%1,%2,%3}, {%4,%5,%6,%7}, {%8,%9}, {%0,%1,%2,%3};"
        : "+f"(d[0]), "+f"(d[1]), "+f"(d[2]), "+f"(d[3])
        : "r"(a[0]), "r"(a[1]), "r"(a[2]), "r"(a[3]), "r"(b[0]), "r"(b[1]));
}
__device__ __forceinline__ void ldsm_x4(unsigned* r, unsigned addr) {
    asm volatile("ldmatrix.sync.aligned.m8n8.x4.shared.b16 {%0,%1,%2,%3}, [%4];"
                 : "=r"(r[0]), "=r"(r[1]), "=r"(r[2]), "=r"(r[3]) : "r"(addr));
}
__device__ __forceinline__ void cp16(unsigned sdst, const void* gsrc) {
    asm volatile("cp.async.cg.shared.global [%0], [%1], 16;" :: "r"(sdst), "l"(gsrc) : "memory");
}
__device__ __forceinline__ int tri_off(int bi) { return bi * NT - (bi * (bi - 1)) / 2; }
__device__ __forceinline__ void decode_pair(int t, int& bi, int& bj) {
    int b = (int)((2.0f * NT + 1.0f
                   - sqrtf(fmaxf((2.0f * NT + 1.0f) * (2.0f * NT + 1.0f) - 8.0f * (float)t, 0.0f)))
                  * 0.5f);
    if (b < 0) b = 0; if (b > NT - 1) b = NT - 1;
    while (b + 1 <= NT - 1 && tri_off(b + 1) <= t) b++;
    while (tri_off(b) > t) b--;
    bi = b;
    bj = b + (t - tri_off(b));
}

// ---------------------------------------------------------------------------
// Prep: Xs = X*sqrt(params) -> bf16, per-tile 8-row XOR swizzle.
// g_sq2[i] = -log2e*||Xs_i||^2 ; g_th[i] = half(target[i]).
// ---------------------------------------------------------------------------
__global__ void prep_kernel(const float* __restrict__ X,
                            const float* __restrict__ params,
                            const float* __restrict__ target) {
    if (blockIdx.x == 0 && threadIdx.x == 0) { g_num = 0.0; g_den = 0.0; g_ctr = 0u; }
    const int g   = blockIdx.x * blockDim.x + threadIdx.x;  // 0..32767
    const int row = g >> 2;
    const int q   = g & 3;

    const float4* P4 = (const float4*)params;
    const float4* X4 = (const float4*)(X + row * DD + q * 16);

    float s = 0.0f;
    unsigned pk[8];
    #pragma unroll
    for (int i = 0; i < 4; i++) {
        float4 p = P4[q * 4 + i];
        float4 x = X4[i];
        float a = x.x * sqrtf(p.x);
        float b = x.y * sqrtf(p.y);
        float c = x.z * sqrtf(p.z);
        float d = x.w * sqrtf(p.w);
        s += a * a + b * b + c * c + d * d;
        __nv_bfloat162 lo = __float22bfloat162_rn(make_float2(a, b));
        __nv_bfloat162 hi = __float22bfloat162_rn(make_float2(c, d));
        pk[i * 2]     = *(unsigned*)&lo;
        pk[i * 2 + 1] = *(unsigned*)&hi;
    }

    const int tile = row >> 7, ri = row & 127;
    unsigned char* tb = g_Xsb + (size_t)tile * TILE_BYTES;
    const unsigned e8a = (unsigned)(q * 2), e8b = e8a + 1;
    *(uint4*)(tb + ri * 128 + ((e8a ^ (unsigned)(ri & 7)) << 4)) =
        make_uint4(pk[0], pk[1], pk[2], pk[3]);
    *(uint4*)(tb + ri * 128 + ((e8b ^ (unsigned)(ri & 7)) << 4)) =
        make_uint4(pk[4], pk[5], pk[6], pk[7]);

    s += __shfl_xor_sync(0xFFFFFFFFu, s, 1);
    s += __shfl_xor_sync(0xFFFFFFFFu, s, 2);
    if (q == 0) {
        g_sq2[row] = NLOG2E * s;
        g_th[row]  = __float2half(target[row]);
    }
}

// ---------------------------------------------------------------------------
// Persistent HMMA tile kernel, cp.async double-buffered.
// Tile processed in two row-halves (32 live accumulators each) to stay well
// under the 128-reg cap (no local-memory spills). Per-row warp vote skips the
// exp+reduction block when every arg < SKIP_THR (fp16 underflow-equivalent).
// ---------------------------------------------------------------------------
__global__ __launch_bounds__(256, 2)
void tile_kernel(const float* __restrict__ target, float* __restrict__ out) {
    extern __shared__ __align__(16) unsigned char smem[];  // 2 x (A 16KB | B 16KB)

    const int tid  = threadIdx.x;
    const int wid  = tid >> 5;
    const int lane = tid & 31;
    const int wr   = wid >> 2;
    const int wc   = wid & 3;
    const int gid  = lane >> 2;
    const int tig  = lane & 3;

    const int l7    = lane & 7;
    const int a_row = 64 * wr + 8 * ((lane >> 3) & 1) + l7;
    const int a_cp  = lane >> 4;
    const int b_row = 32 * wc + 8 * (lane >> 4) + l7;
    const int b_cp  = (lane >> 3) & 1;

    const unsigned sbase = smem_u32(smem);
    const __half hone = __float2half(1.0f);

    float ln = 0.0f, ld = 0.0f;
    unsigned pb = 0;

    int t = blockIdx.x;
    int bi, bj;
    decode_pair(t, bi, bj);
    {   // prologue: stage first pair into buf 0
        const unsigned char* gA = g_Xsb + (size_t)bi * TILE_BYTES;
        const unsigned char* gB = g_Xsb + (size_t)bj * TILE_BYTES;
        #pragma unroll
        for (int s = 0; s < 4; s++) {
            int c = (tid + 256 * s) * 16;
            cp16(sbase + c, gA + c);
            cp16(sbase + TILE_BYTES + c, gB + c);
        }
        asm volatile("cp.async.commit_group;" ::: "memory");
    }

    for (; t < NPAIRS; t += GRID_TILE) {
        const int tnx = t + GRID_TILE;
        int nbi = 0, nbj = 0;
        if (tnx < NPAIRS) {
            decode_pair(tnx, nbi, nbj);
            const unsigned nb = sbase + (pb ^ 1) * BUF_BYTES;
            const unsigned char* gA = g_Xsb + (size_t)nbi * TILE_BYTES;
            const unsigned char* gB = g_Xsb + (size_t)nbj * TILE_BYTES;
            #pragma unroll
            for (int s = 0; s < 4; s++) {
                int c = (tid + 256 * s) * 16;
                cp16(nb + c, gA + c);
                cp16(nb + TILE_BYTES + c, gB + c);
            }
        }
        asm volatile("cp.async.commit_group;" ::: "memory");
        asm volatile("cp.async.wait_group 1;" ::: "memory");
        __syncthreads();

        const unsigned sA = sbase + pb * BUF_BYTES;
        const unsigned sB = sA + TILE_BYTES;

        // ---- per-column scalars (live across both halves) ----
        float sqjv[8];
        __half2 tj2[4];
        #pragma unroll
        for (int ca = 0; ca < 4; ca++) {
            const int cg = bj * TILE + 32 * wc + 8 * ca + 2 * tig;
            sqjv[2 * ca]     = __ldg(g_sq2 + cg);
            sqjv[2 * ca + 1] = __ldg(g_sq2 + cg + 1);
            tj2[ca]          = *(const __half2*)(g_th + cg);
        }

        const bool diag = (bi == bj);
        __half2 rd2 = __float2half2_rn(0.0f);
        float tn = 0.0f;

        // ================= two row-halves: MMA + fused epilogue =============
        #pragma unroll
        for (int h = 0; h < 2; h++) {
            float acc[2][4][4];
            #pragma unroll
            for (int ra = 0; ra < 2; ra++)
                #pragma unroll
                for (int ca = 0; ca < 4; ca++)
                    #pragma unroll
                    for (int qq = 0; qq < 4; qq++) acc[ra][ca][qq] = 0.0f;

            #pragma unroll
            for (int ks = 0; ks < 4; ks++) {
                const unsigned axor = (((unsigned)(2 * ks + a_cp)) ^ (unsigned)l7) << 4;
                const unsigned bxor = (((unsigned)(2 * ks + b_cp)) ^ (unsigned)l7) << 4;
                unsigned a[2][4];
                #pragma unroll
                for (int ra = 0; ra < 2; ra++)
                    ldsm_x4(a[ra], sA + (unsigned)(a_row + 16 * (2 * h + ra)) * 128 + axor);
                unsigned b[2][4];
                #pragma unroll
                for (int cb = 0; cb < 2; cb++)
                    ldsm_x4(b[cb], sB + (unsigned)(b_row + 16 * cb) * 128 + bxor);
                #pragma unroll
                for (int ra = 0; ra < 2; ra++)
                    #pragma unroll
                    for (int ca = 0; ca < 4; ca++)
                        mma16816(acc[ra][ca], a[ra], &b[ca >> 1][(ca & 1) * 2]);
            }

            #pragma unroll
            for (int ra = 0; ra < 2; ra++) {
                const int rg = 2 * h + ra;                // 0..3
                const int r0 = 64 * wr + 16 * rg + gid;
                const int r1 = r0 + 8;
                const float sqi0 = __ldg(g_sq2 + bi * TILE + r0);
                const float sqi1 = __ldg(g_sq2 + bi * TILE + r1);

                // args for this row-pair (16 values), one vote for all of them
                float arg[4][4];
                float m = -1e30f;
                #pragma unroll
                for (int ca = 0; ca < 4; ca++) {
                    const float* d = acc[ra][ca];
                    arg[ca][0] = fmaf(d[0], TWOLOG2E, sqi0 + sqjv[2 * ca]);
                    arg[ca][1] = fmaf(d[1], TWOLOG2E, sqi0 + sqjv[2 * ca + 1]);
                    arg[ca][2] = fmaf(d[2], TWOLOG2E, sqi1 + sqjv[2 * ca]);
                    arg[ca][3] = fmaf(d[3], TWOLOG2E, sqi1 + sqjv[2 * ca + 1]);
                    m = fmaxf(m, fmaxf(fmaxf(arg[ca][0], arg[ca][1]),
                                       fmaxf(arg[ca][2], arg[ca][3])));
                }

                if (diag || __any_sync(0xFFFFFFFFu, m > SKIP_THR)) {
                    const float ti0 = __ldg(target + bi * TILE + r0);
                    const float ti1 = __ldg(target + bi * TILE + r1);
                    __half2 rn0 = __float2half2_rn(0.0f);
                    __half2 rn1 = __float2half2_rn(0.0f);
                    #pragma unroll
                    for (int ca = 0; ca < 4; ca++) {
                        __half2 k0 = h2exp2(__floats2half2_rn(arg[ca][0], arg[ca][1]));
                        __half2 k1 = h2exp2(__floats2half2_rn(arg[ca][2], arg[ca][3]));
                        if (diag) {   // reference keeps eye() on the diagonal
                            const int c0 = 32 * wc + 8 * ca + 2 * tig;
                            if (r0 == c0)     k0 = __halves2half2(hone, __high2half(k0));
                            if (r0 == c0 + 1) k0 = __halves2half2(__low2half(k0), hone);
                            if (r1 == c0)     k1 = __halves2half2(hone, __high2half(k1));
                            if (r1 == c0 + 1) k1 = __halves2half2(__low2half(k1), hone);
                        }
                        rn0 = __hfma2(tj2[ca], k0, rn0);
                        rn1 = __hfma2(tj2[ca], k1, rn1);
                        rd2 = __hfma2(k0, k0, rd2);
                        rd2 = __hfma2(k1, k1, rd2);
                    }
                    const float2 f0 = __half22float2(rn0);
                    const float2 f1 = __half22float2(rn1);
                    tn = fmaf(ti0, f0.x + f0.y, tn);
                    tn = fmaf(ti1, f1.x + f1.y, tn);
                }
            }
        }

        const float w = diag ? 1.0f : 2.0f;   // symmetry: off-diag pairs x2
        const float2 fd = __half22float2(rd2);
        ln = fmaf(w, tn, ln);
        ld = fmaf(w, fd.x + fd.y, ld);

        __syncthreads();   // reads of buf[pb] done before restage
        pb ^= 1;
        bi = nbi; bj = nbj;
    }

    // block reduction -> double atomics; last CTA writes the final scalar
    #pragma unroll
    for (int o = 16; o; o >>= 1) {
        ln += __shfl_xor_sync(0xFFFFFFFFu, ln, o);
        ld += __shfl_xor_sync(0xFFFFFFFFu, ld, o);
    }
    __shared__ float rn_[8], rd_[8];
    if (lane == 0) { rn_[wid] = ln; rd_[wid] = ld; }
    __syncthreads();
    if (tid == 0) {
        float a = 0.0f, b = 0.0f;
        #pragma unroll
        for (int k = 0; k < 8; k++) { a += rn_[k]; b += rd_[k]; }
        atomicAdd(&g_num, (double)a);
        atomicAdd(&g_den, (double)b);
        __threadfence();
        const unsigned done = atomicAdd(&g_ctr, 1u);
        if (done == GRID_TILE - 1) {
            const double num = *(volatile double*)&g_num;
            const double den = *(volatile double*)&g_den;
            out[0] = (float)(-num / ((double)NN * sqrt(den)));
        }
    }
}

extern "C" void kernel_launch(void* const* d_in, const int* in_sizes, int n_in,
                              void* d_out, int out_size) {
    const float* X      = (const float*)d_in[0];
    const float* target = (const float*)d_in[1];
    const float* params = (const float*)d_in[2];
    float* out = (float*)d_out;

    cudaFuncSetAttribute(tile_kernel,
                         cudaFuncAttributeMaxDynamicSharedMemorySize, 2 * BUF_BYTES);

    prep_kernel<<<128, 256>>>(X, params, target);
    tile_kernel<<<GRID_TILE, 256, 2 * BUF_BYTES>>>(target, out);
}

// round 15
// speedup vs baseline: 5.1170x; 1.0655x over previous
#include <cuda_runtime.h>
#include <cuda_bf16.h>
#include <cuda_fp16.h>
#include <math.h>

#define NN 8192
#define DD 64
#define TILE 128
#define NT (NN / TILE)                 // 64 tiles per dim
#define NPAIRS (NT * (NT + 1) / 2)     // 2080 triangular tile pairs
#define TILE_BYTES (TILE * DD * 2)     // 16 KB: 128 rows x 64 bf16 (128 B/row)
#define BUF_BYTES (2 * TILE_BYTES)     // A + B per stage
#define GRID_TILE 296                  // persistent, 2 CTAs/SM; 2080 = 8*8 + 288*7
#define NLOG2E (-1.4426950408889634f)
#define TWOLOG2E 2.8853900817779268f
#define SKIP_THR (-25.0f)              // exp2(arg) < 2^-25 -> fp16 flushes to ~0 anyway

__device__ __align__(16) unsigned char g_Xsb[NT * TILE_BYTES]; // swizzled bf16 tiles (4 MB, L2-resident)
__device__ float g_sq2[NN];            // -log2e * ||Xs_i||^2
__device__ __half g_th[NN];            // target in fp16
__device__ double g_num, g_den;
__device__ unsigned g_ctr;

__device__ __forceinline__ unsigned smem_u32(const void* p) {
    unsigned a;
    asm("{ .reg .u64 t; cvta.to.shared.u64 t, %1; cvt.u32.u64 %0, t; }" : "=r"(a) : "l"(p));
    return a;
}
__device__ __forceinline__ void mma16816(float* d, const unsigned* a, const unsigned* b) {
    asm volatile(
        "mma.sync.aligned.m16n8k16.row.col.f32.bf16.bf16.f32 "
        "{%0,%1,%2,%3}, {%4,%5,%6,%7}, {%8,%9}, {%0,%1,%2,%3};"
        : "+f"(d[0]), "+f"(d[1]), "+f"(d[2]), "+f"(d[3])
        : "r"(a[0]), "r"(a[1]), "r"(a[2]), "r"(a[3]), "r"(b[0]), "r"(b[1]));
}
__device__ __forceinline__ void ldsm_x4(unsigned* r, unsigned addr) {
    asm volatile("ldmatrix.sync.aligned.m8n8.x4.shared.b16 {%0,%1,%2,%3}, [%4];"
                 : "=r"(r[0]), "=r"(r[1]), "=r"(r[2]), "=r"(r[3]) : "r"(addr));
}
__device__ __forceinline__ void cp16(unsigned sdst, const void* gsrc) {
    asm volatile("cp.async.cg.shared.global [%0], [%1], 16;" :: "r"(sdst), "l"(gsrc) : "memory");
}
__device__ __forceinline__ int tri_off(int bi) { return bi * NT - (bi * (bi - 1)) / 2; }
__device__ __forceinline__ void decode_pair(int t, int& bi, int& bj) {
    int b = (int)((2.0f * NT + 1.0f
                   - sqrtf(fmaxf((2.0f * NT + 1.0f) * (2.0f * NT + 1.0f) - 8.0f * (float)t, 0.0f)))
                  * 0.5f);
    if (b < 0) b = 0; if (b > NT - 1) b = NT - 1;
    while (b + 1 <= NT - 1 && tri_off(b + 1) <= t) b++;
    while (tri_off(b) > t) b--;
    bi = b;
    bj = b + (t - tri_off(b));
}

// ---------------------------------------------------------------------------
// Prep: Xs = X*sqrt(params) -> bf16, per-tile 8-row XOR swizzle.
// ---------------------------------------------------------------------------
__global__ void prep_kernel(const float* __restrict__ X,
                            const float* __restrict__ params,
                            const float* __restrict__ target) {
    if (blockIdx.x == 0 && threadIdx.x == 0) { g_num = 0.0; g_den = 0.0; g_ctr = 0u; }
    const int g   = blockIdx.x * blockDim.x + threadIdx.x;
    const int row = g >> 2;
    const int q   = g & 3;

    const float4* P4 = (const float4*)params;
    const float4* X4 = (const float4*)(X + row * DD + q * 16);

    float s = 0.0f;
    unsigned pk[8];
    #pragma unroll
    for (int i = 0; i < 4; i++) {
        float4 p = P4[q * 4 + i];
        float4 x = X4[i];
        float a = x.x * sqrtf(p.x);
        float b = x.y * sqrtf(p.y);
        float c = x.z * sqrtf(p.z);
        float d = x.w * sqrtf(p.w);
        s += a * a + b * b + c * c + d * d;
        __nv_bfloat162 lo = __float22bfloat162_rn(make_float2(a, b));
        __nv_bfloat162 hi = __float22bfloat162_rn(make_float2(c, d));
        pk[i * 2]     = *(unsigned*)&lo;
        pk[i * 2 + 1] = *(unsigned*)&hi;
    }

    const int tile = row >> 7, ri = row & 127;
    unsigned char* tb = g_Xsb + (size_t)tile * TILE_BYTES;
    const unsigned e8a = (unsigned)(q * 2), e8b = e8a + 1;
    *(uint4*)(tb + ri * 128 + ((e8a ^ (unsigned)(ri & 7)) << 4)) =
        make_uint4(pk[0], pk[1], pk[2], pk[3]);
    *(uint4*)(tb + ri * 128 + ((e8b ^ (unsigned)(ri & 7)) << 4)) =
        make_uint4(pk[4], pk[5], pk[6], pk[7]);

    s += __shfl_xor_sync(0xFFFFFFFFu, s, 1);
    s += __shfl_xor_sync(0xFFFFFFFFu, s, 2);
    if (q == 0) {
        g_sq2[row] = NLOG2E * s;
        g_th[row]  = __float2half(target[row]);
    }
}

// ---------------------------------------------------------------------------
// Persistent HMMA tile kernel. Each CTA owns a CONTIGUOUS lexicographic run
// of pairs (row-band): A tile restaged only when bi changes (per-buffer bi
// tag); B double-buffered via cp.async. Scalar LDGs hoisted ahead of MMA.
// ---------------------------------------------------------------------------
__global__ __launch_bounds__(256, 2)
void tile_kernel(const float* __restrict__ target, float* __restrict__ out) {
    extern __shared__ __align__(16) unsigned char smem[];  // 2 x (A 16KB | B 16KB)

    const int tid  = threadIdx.x;
    const int wid  = tid >> 5;
    const int lane = tid & 31;
    const int wr   = wid >> 2;
    const int wc   = wid & 3;
    const int gid  = lane >> 2;
    const int tig  = lane & 3;

    const int l7    = lane & 7;
    const int a_row = 64 * wr + 8 * ((lane >> 3) & 1) + l7;
    const int a_cp  = lane >> 4;
    const int b_row = 32 * wc + 8 * (lane >> 4) + l7;
    const int b_cp  = (lane >> 3) & 1;

    const unsigned sbase = smem_u32(smem);
    const __half hone = __float2half(1.0f);

    float ln = 0.0f, ld = 0.0f;
    unsigned pb = 0;

    // contiguous run: first 8 CTAs get 8 pairs, rest 7   (8*8 + 288*7 = 2080)
    const int c     = blockIdx.x;
    const int start = (c < 8) ? 8 * c : 7 * c + 8;
    const int len   = (c < 8) ? 8 : 7;

    int bi, bj;
    decode_pair(start, bi, bj);
    int tagA0 = -1, tagA1 = -1;   // bi resident in buf0.A / buf1.A

    {   // prologue: stage A+B of first pair into buf 0
        const unsigned char* gA = g_Xsb + (size_t)bi * TILE_BYTES;
        const unsigned char* gB = g_Xsb + (size_t)bj * TILE_BYTES;
        #pragma unroll
        for (int s = 0; s < 4; s++) {
            int cc = (tid + 256 * s) * 16;
            cp16(sbase + cc, gA + cc);
            cp16(sbase + TILE_BYTES + cc, gB + cc);
        }
        asm volatile("cp.async.commit_group;" ::: "memory");
        tagA0 = bi;
    }

    for (int li = 0; li < len; li++) {
        // next pair in lexicographic order
        int nbi = bi, nbj = bj + 1;
        if (nbj == NT) { nbi = bi + 1; nbj = nbi; }

        if (li + 1 < len) {   // prefetch next pair into buf^1
            const unsigned nb = sbase + (pb ^ 1) * BUF_BYTES;
            const int tagN = (pb ^ 1) ? tagA1 : tagA0;
            if (tagN != nbi) {   // A changed (or cold buffer): restage A
                const unsigned char* gA = g_Xsb + (size_t)nbi * TILE_BYTES;
                #pragma unroll
                for (int s = 0; s < 4; s++) {
                    int cc = (tid + 256 * s) * 16;
                    cp16(nb + cc, gA + cc);
                }
                if (pb ^ 1) tagA1 = nbi; else tagA0 = nbi;
            }
            const unsigned char* gB = g_Xsb + (size_t)nbj * TILE_BYTES;
            #pragma unroll
            for (int s = 0; s < 4; s++) {
                int cc = (tid + 256 * s) * 16;
                cp16(nb + TILE_BYTES + cc, gB + cc);
            }
        }
        asm volatile("cp.async.commit_group;" ::: "memory");

        // hoisted per-column scalars for CURRENT bj (overlap with cp wait)
        float sqjv[8];
        __half2 tj2[4];
        #pragma unroll
        for (int ca = 0; ca < 4; ca++) {
            const int cg = bj * TILE + 32 * wc + 8 * ca + 2 * tig;
            sqjv[2 * ca]     = __ldg(g_sq2 + cg);
            sqjv[2 * ca + 1] = __ldg(g_sq2 + cg + 1);
            tj2[ca]          = *(const __half2*)(g_th + cg);
        }

        asm volatile("cp.async.wait_group 1;" ::: "memory");
        __syncthreads();

        // hoisted per-row scalars (latency hidden under MMA below)
        float sqiv[8];
        #pragma unroll
        for (int rg = 0; rg < 4; rg++) {
            sqiv[2 * rg]     = __ldg(g_sq2 + bi * TILE + 64 * wr + 16 * rg + gid);
            sqiv[2 * rg + 1] = __ldg(g_sq2 + bi * TILE + 64 * wr + 16 * rg + gid + 8);
        }

        const unsigned sA = sbase + pb * BUF_BYTES;
        const unsigned sB = sA + TILE_BYTES;
        const bool diag = (bi == bj);
        __half2 rd2 = __float2half2_rn(0.0f);
        float tn = 0.0f;

        // ============ two row-halves: MMA + fused epilogue ============
        #pragma unroll
        for (int h = 0; h < 2; h++) {
            float acc[2][4][4];
            #pragma unroll
            for (int ra = 0; ra < 2; ra++)
                #pragma unroll
                for (int ca = 0; ca < 4; ca++)
                    #pragma unroll
                    for (int qq = 0; qq < 4; qq++) acc[ra][ca][qq] = 0.0f;

            #pragma unroll
            for (int ks = 0; ks < 4; ks++) {
                const unsigned axor = (((unsigned)(2 * ks + a_cp)) ^ (unsigned)l7) << 4;
                const unsigned bxor = (((unsigned)(2 * ks + b_cp)) ^ (unsigned)l7) << 4;
                unsigned a[2][4];
                #pragma unroll
                for (int ra = 0; ra < 2; ra++)
                    ldsm_x4(a[ra], sA + (unsigned)(a_row + 16 * (2 * h + ra)) * 128 + axor);
                unsigned b[2][4];
                #pragma unroll
                for (int cb = 0; cb < 2; cb++)
                    ldsm_x4(b[cb], sB + (unsigned)(b_row + 16 * cb) * 128 + bxor);
                #pragma unroll
                for (int ra = 0; ra < 2; ra++)
                    #pragma unroll
                    for (int ca = 0; ca < 4; ca++)
                        mma16816(acc[ra][ca], a[ra], &b[ca >> 1][(ca & 1) * 2]);
            }

            #pragma unroll
            for (int ra = 0; ra < 2; ra++) {
                const int rg = 2 * h + ra;
                const int r0 = 64 * wr + 16 * rg + gid;
                const int r1 = r0 + 8;
                const float sqi0 = sqiv[2 * rg];
                const float sqi1 = sqiv[2 * rg + 1];

                float arg[4][4];
                float m = -1e30f;
                #pragma unroll
                for (int ca = 0; ca < 4; ca++) {
                    const float* d = acc[ra][ca];
                    arg[ca][0] = fmaf(d[0], TWOLOG2E, sqi0 + sqjv[2 * ca]);
                    arg[ca][1] = fmaf(d[1], TWOLOG2E, sqi0 + sqjv[2 * ca + 1]);
                    arg[ca][2] = fmaf(d[2], TWOLOG2E, sqi1 + sqjv[2 * ca]);
                    arg[ca][3] = fmaf(d[3], TWOLOG2E, sqi1 + sqjv[2 * ca + 1]);
                    m = fmaxf(m, fmaxf(fmaxf(arg[ca][0], arg[ca][1]),
                                       fmaxf(arg[ca][2], arg[ca][3])));
                }

                if (diag || __any_sync(0xFFFFFFFFu, m > SKIP_THR)) {
                    const float ti0 = __ldg(target + bi * TILE + r0);
                    const float ti1 = __ldg(target + bi * TILE + r1);
                    __half2 rn0 = __float2half2_rn(0.0f);
                    __half2 rn1 = __float2half2_rn(0.0f);
                    #pragma unroll
                    for (int ca = 0; ca < 4; ca++) {
                        __half2 k0 = h2exp2(__floats2half2_rn(arg[ca][0], arg[ca][1]));
                        __half2 k1 = h2exp2(__floats2half2_rn(arg[ca][2], arg[ca][3]));
                        if (diag) {   // reference keeps eye() on the diagonal
                            const int c0 = 32 * wc + 8 * ca + 2 * tig;
                            if (r0 == c0)     k0 = __halves2half2(hone, __high2half(k0));
                            if (r0 == c0 + 1) k0 = __halves2half2(__low2half(k0), hone);
                            if (r1 == c0)     k1 = __halves2half2(hone, __high2half(k1));
                            if (r1 == c0 + 1) k1 = __halves2half2(__low2half(k1), hone);
                        }
                        rn0 = __hfma2(tj2[ca], k0, rn0);
                        rn1 = __hfma2(tj2[ca], k1, rn1);
                        rd2 = __hfma2(k0, k0, rd2);
                        rd2 = __hfma2(k1, k1, rd2);
                    }
                    const float2 f0 = __half22float2(rn0);
                    const float2 f1 = __half22float2(rn1);
                    tn = fmaf(ti0, f0.x + f0.y, tn);
                    tn = fmaf(ti1, f1.x + f1.y, tn);
                }
            }
        }

        const float w = diag ? 1.0f : 2.0f;   // symmetry: off-diag pairs x2
        const float2 fd = __half22float2(rd2);
        ln = fmaf(w, tn, ln);
        ld = fmaf(w, fd.x + fd.y, ld);

        __syncthreads();   // all reads of buf[pb] done before it is restaged
        pb ^= 1;
        bi = nbi; bj = nbj;
    }

    // block reduction -> double atomics; last CTA writes the final scalar
    #pragma unroll
    for (int o = 16; o; o >>= 1) {
        ln += __shfl_xor_sync(0xFFFFFFFFu, ln, o);
        ld += __shfl_xor_sync(0xFFFFFFFFu, ld, o);
    }
    __shared__ float rn_[8], rd_[8];
    if (lane == 0) { rn_[wid] = ln; rd_[wid] = ld; }
    __syncthreads();
    if (tid == 0) {
        float a = 0.0f, b = 0.0f;
        #pragma unroll
        for (int k = 0; k < 8; k++) { a += rn_[k]; b += rd_[k]; }
        atomicAdd(&g_num, (double)a);
        atomicAdd(&g_den, (double)b);
        __threadfence();
        const unsigned done = atomicAdd(&g_ctr, 1u);
        if (done == GRID_TILE - 1) {
            const double num = *(volatile double*)&g_num;
            const double den = *(volatile double*)&g_den;
            out[0] = (float)(-num / ((double)NN * sqrt(den)));
        }
    }
}

extern "C" void kernel_launch(void* const* d_in, const int* in_sizes, int n_in,
                              void* d_out, int out_size) {
    const float* X      = (const float*)d_in[0];
    const float* target = (const float*)d_in[1];
    const float* params = (const float*)d_in[2];
    float* out = (float*)d_out;

    cudaFuncSetAttribute(tile_kernel,
                         cudaFuncAttributeMaxDynamicSharedMemorySize, 2 * BUF_BYTES);

    prep_kernel<<<128, 256>>>(X, params, target);
    tile_kernel<<<GRID_TILE, 256, 2 * BUF_BYTES>>>(target, out);
}